// round 15
// baseline (speedup 1.0000x reference)
#include <cuda_runtime.h>
#include <cstdint>

#define BN 4
#define CC 256
#define NN 4096
#define LOG2E 1.4426950408889634f

// ---------------- scratch ----------------
__device__ unsigned g_qh[BN * NN * 16];         // [b][n][cw] hi bf16 pair (c even/odd packed)
__device__ unsigned g_ql[BN * NN * 16];         // lo residual
__device__ unsigned g_kh[BN * NN * 16];         // k pre-scaled by log2(e)
__device__ unsigned g_kl[BN * NN * 16];
__device__ unsigned g_vtp[BN * CC * (NN / 2)]; // [b][c][m2] = pack(v[c][2m2], v[c][2m2+1])

__device__ __forceinline__ unsigned bf16bits(float f) {
    unsigned u = __float_as_uint(f);
    return (u + 0x7fffu + ((u >> 16) & 1u)) >> 16;
}

__device__ __forceinline__ unsigned sptr(const void* p) {
    unsigned a;
    asm("{ .reg .u64 t; cvta.to.shared.u64 t, %1; cvt.u32.u64 %0, t; }" : "=r"(a) : "l"(p));
    return a;
}

__device__ __forceinline__ float ex2f(float x) {
    float y;
    asm("ex2.approx.f32 %0, %1;" : "=f"(y) : "f"(x));
    return y;
}

__device__ __forceinline__ void ldsm4(unsigned a, unsigned& r0, unsigned& r1, unsigned& r2, unsigned& r3) {
    asm volatile("ldmatrix.sync.aligned.m8n8.x4.shared.b16 {%0,%1,%2,%3}, [%4];"
                 : "=r"(r0), "=r"(r1), "=r"(r2), "=r"(r3) : "r"(a));
}

__device__ __forceinline__ void mma16816(float* d, unsigned a0, unsigned a1, unsigned a2, unsigned a3,
                                         unsigned b0, unsigned b1) {
    asm volatile(
        "mma.sync.aligned.m16n8k16.row.col.f32.bf16.bf16.f32 "
        "{%0,%1,%2,%3}, {%4,%5,%6,%7}, {%8,%9}, {%0,%1,%2,%3};\n"
        : "+f"(d[0]), "+f"(d[1]), "+f"(d[2]), "+f"(d[3])
        : "r"(a0), "r"(a1), "r"(a2), "r"(a3), "r"(b0), "r"(b1));
}

__device__ __forceinline__ void cpa16(unsigned dst, const void* src) {
    asm volatile("cp.async.cg.shared.global [%0], [%1], 16;" :: "r"(dst), "l"(src));
}

// ---------------- K_PROJ: fused, load-balanced q/k + v projections ----------------
// grid (128, BN): bx<64 -> q,k role (64-n tile); bx>=64 -> v role (64-n tile, all 256 c).
__global__ void __launch_bounds__(256) k_proj(const float* __restrict__ x,
                                              const float* __restrict__ Wq, const float* __restrict__ bq,
                                              const float* __restrict__ Wk, const float* __restrict__ bk,
                                              const float* __restrict__ Wv, const float* __restrict__ bv) {
    __shared__ __align__(16) char smbuf[42496];
    int b = blockIdx.y;
    int tid = threadIdx.x;
    const float* xb = x + (size_t)b * CC * NN;

    if (blockIdx.x < 64) {
        // ======== q,k role (identical to validated k_qk) ========
        float (*Ws)[33] = (float(*)[33])smbuf;           // 64 x 33
        float (*Xs)[68] = (float(*)[68])(smbuf + 8448);  // 32 x 68
        int n0 = blockIdx.x * 64;
        float acc[4][4];
#pragma unroll
        for (int i = 0; i < 4; i++)
#pragma unroll
            for (int j = 0; j < 4; j++) acc[i][j] = 0.f;
        int tr = tid >> 4, tn = tid & 15;
        for (int k0 = 0; k0 < CC; k0 += 32) {
            for (int i = tid; i < 64 * 32; i += 256) {
                int r = i >> 5, kk = i & 31;
                Ws[r][kk] = (r < 32) ? Wq[r * CC + k0 + kk] : Wk[(r - 32) * CC + k0 + kk];
            }
            {
                int kk = tid >> 3, nn = (tid & 7) * 8;
                *(float4*)&Xs[kk][nn] = *(const float4*)&xb[(size_t)(k0 + kk) * NN + n0 + nn];
                *(float4*)&Xs[kk][nn + 4] = *(const float4*)&xb[(size_t)(k0 + kk) * NN + n0 + nn + 4];
            }
            __syncthreads();
#pragma unroll
            for (int kk = 0; kk < 32; kk++) {
                float wf[4], xf[4];
#pragma unroll
                for (int i = 0; i < 4; i++) wf[i] = Ws[tr * 4 + i][kk];
                *(float4*)&xf[0] = *(float4*)&Xs[kk][tn * 4];
#pragma unroll
                for (int i = 0; i < 4; i++)
#pragma unroll
                    for (int j = 0; j < 4; j++) acc[i][j] += wf[i] * xf[j];
            }
            __syncthreads();
        }
#pragma unroll
        for (int i = 0; i < 4; i++) {
            int r = tr * 4 + i;
            float bias = (r < 32) ? bq[r] : bk[r - 32];
            float scale = (r < 32) ? 1.f : LOG2E;  // fold log2e into k so exp(s) = ex2(s')
#pragma unroll
            for (int j = 0; j < 4; j++) acc[i][j] = (acc[i][j] + bias) * scale;
        }
        unsigned hw[2][4], lw[2][4];
#pragma unroll
        for (int p = 0; p < 2; p++)
#pragma unroll
            for (int j = 0; j < 4; j++) {
                float a0 = acc[2 * p][j], a1 = acc[2 * p + 1][j];
                unsigned h0 = bf16bits(a0);
                unsigned h1 = bf16bits(a1);
                float f0 = __uint_as_float(h0 << 16);
                float f1 = __uint_as_float(h1 << 16);
                unsigned l0 = bf16bits(a0 - f0);
                unsigned l1 = bf16bits(a1 - f1);
                hw[p][j] = h0 | (h1 << 16);
                lw[p][j] = l0 | (l1 << 16);
            }
        unsigned* st = (unsigned*)&Xs[0][0];  // 64 x 17 staging (aliases Xs)
        bool isq = (tr < 8);
        int cw0 = (isq ? tr : tr - 8) * 2;
        for (int ph = 0; ph < 4; ph++) {
            bool mine = (ph < 2) ? isq : !isq;
            bool lo = (ph & 1);
            __syncthreads();
            if (mine) {
#pragma unroll
                for (int p = 0; p < 2; p++)
#pragma unroll
                    for (int j = 0; j < 4; j++)
                        st[(tn * 4 + j) * 17 + cw0 + p] = lo ? lw[p][j] : hw[p][j];
            }
            __syncthreads();
            unsigned* dst = (ph == 0 ? g_qh : ph == 1 ? g_ql : ph == 2 ? g_kh : g_kl)
                            + ((size_t)b * NN + n0) * 16;
            int row = tid >> 2, w0 = (tid & 3) * 4;
            unsigned t0 = st[row * 17 + w0 + 0], t1 = st[row * 17 + w0 + 1];
            unsigned t2 = st[row * 17 + w0 + 2], t3 = st[row * 17 + w0 + 3];
            *(uint4*)&dst[row * 16 + w0] = make_uint4(t0, t1, t2, t3);
        }
    } else {
        // ======== v role (identical to validated k_v 8x8) ========
        float (*Ws)[33] = (float(*)[33])smbuf;            // 256 x 33
        float (*Xs)[68] = (float(*)[68])(smbuf + 33792);  // 32 x 68
        int n0 = (blockIdx.x - 64) * 64;
        float acc[8][8];
#pragma unroll
        for (int i = 0; i < 8; i++)
#pragma unroll
            for (int j = 0; j < 8; j++) acc[i][j] = 0.f;
        int tr = tid >> 3, tc = tid & 7;  // 8 c-rows x 8 n-cols per thread
        for (int k0 = 0; k0 < CC; k0 += 32) {
            {
                const float4* src = (const float4*)&Wv[(size_t)tid * CC + k0];
#pragma unroll
                for (int q = 0; q < 8; q++) {
                    float4 w4 = src[q];
                    Ws[tid][q * 4 + 0] = w4.x;
                    Ws[tid][q * 4 + 1] = w4.y;
                    Ws[tid][q * 4 + 2] = w4.z;
                    Ws[tid][q * 4 + 3] = w4.w;
                }
            }
            {
                int kk = tid >> 3, nn = (tid & 7) * 8;
                *(float4*)&Xs[kk][nn] = *(const float4*)&xb[(size_t)(k0 + kk) * NN + n0 + nn];
                *(float4*)&Xs[kk][nn + 4] = *(const float4*)&xb[(size_t)(k0 + kk) * NN + n0 + nn + 4];
            }
            __syncthreads();
#pragma unroll
            for (int kk = 0; kk < 32; kk++) {
                float xf[8];
                *(float4*)&xf[0] = *(float4*)&Xs[kk][tc * 8];
                *(float4*)&xf[4] = *(float4*)&Xs[kk][tc * 8 + 4];
#pragma unroll
                for (int i = 0; i < 8; i++) {
                    float wv = Ws[tr * 8 + i][kk];
#pragma unroll
                    for (int j = 0; j < 8; j++) acc[i][j] += wv * xf[j];
                }
            }
            __syncthreads();
        }
#pragma unroll
        for (int i = 0; i < 8; i++) {
            int c = tr * 8 + i;
            float bias = bv[c];
            unsigned w[4];
#pragma unroll
            for (int p = 0; p < 4; p++)
                w[p] = bf16bits(acc[i][2 * p] + bias) | (bf16bits(acc[i][2 * p + 1] + bias) << 16);
            *(uint4*)&g_vtp[((size_t)b * CC + c) * (NN / 2) + (n0 >> 1) + tc * 4] =
                make_uint4(w[0], w[1], w[2], w[3]);
        }
    }
}

// ---------------- KO7: j=128/512thr; single-barrier phase-B; phase-A m-chunk 256 (unchanged) ----------------
struct Ko7Smem {
    unsigned ksh[128 * 20];
    unsigned ksl[128 * 20];
    unsigned qsh[3][64 * 20];
    unsigned qsl[3][64 * 20];
    unsigned As[2][128 * 36];  // bf16 P tile, double buffered
    unsigned Bs[3][256 * 36];  // v chunks triple buffered; phase-A q stream; epilogue fp32 staging
    float zsh[128];
};
#define QBUF_B (64 * 20 * 4)
#define VBUF_B (256 * 36 * 4)
#define ASBUF_B (128 * 36 * 4)
#define PA_HL  (256 * 20 * 4)
#define PA_BUF (2 * PA_HL)

__global__ void __launch_bounds__(512) k_o7(float* __restrict__ AM, const float* __restrict__ x,
                                            const float* __restrict__ gptr, float* __restrict__ outp) {
    extern __shared__ Ko7Smem s7[];
    Ko7Smem& S = s7[0];
    int jb = blockIdx.x, b = blockIdx.y;
    int j0 = jb * 128;
    int tid = threadIdx.x;
    if (tid < 128) S.zsh[tid] = 0.f;
    // K tiles once
    for (int u = tid; u < 1024; u += 512) {
        int bufl = u >> 9, r = (u >> 2) & 127, w = (u & 3) * 4;
        const unsigned* src = (bufl ? g_kl : g_kh) + ((size_t)b * NN + j0 + r) * 16 + w;
        unsigned* dst = (bufl ? S.ksl : S.ksh) + r * 20 + w;
        *(uint4*)dst = *(const uint4*)src;
    }
    __syncthreads();

    int warp = tid >> 5, lane = tid & 31, gid = lane >> 2, tg = lane & 3;
    int j0s = (warp & 7) * 16;
    int m0sB = (warp >> 3) * 32, m0sA = (warp >> 3) * 128;
    int wj = warp >> 2, wc = warp & 3;
    unsigned aoffS = ((j0s + (lane & 15)) * 20 + ((lane >> 4) << 2)) * 4;
    unsigned kshA = sptr(S.ksh) + aoffS, kslA = sptr(S.ksl) + aoffS;
    unsigned boffS = (((lane & 7) + ((lane & 16) >> 1)) * 20 + ((lane & 8) >> 1)) * 4;
    unsigned AsA = sptr(S.As[0]) + ((lane & 15) * 36 + ((lane >> 4) << 2)) * 4;
    unsigned boffO = ((((lane & 7) + ((lane & 16) >> 1)) + wc * 64) * 36 + ((lane & 8) >> 1)) * 4;
    unsigned qshS = sptr(S.qsh[0]), qslS = sptr(S.qsl[0]), BsS = sptr(S.Bs[0]);
    const unsigned* vbp = g_vtp + (size_t)b * CC * (NN / 2);

    // hoisted k A-fragments (loop-invariant across BOTH phases)
    unsigned ah2[2][4], al2[2][4];
    ldsm4(kshA + 0, ah2[0][0], ah2[0][1], ah2[0][2], ah2[0][3]);
    ldsm4(kshA + 32, ah2[1][0], ah2[1][1], ah2[1][2], ah2[1][3]);
    ldsm4(kslA + 0, al2[0][0], al2[0][1], al2[0][2], al2[0][3]);
    ldsm4(kslA + 32, al2[1][0], al2[1][1], al2[1][2], al2[1][3]);

    // ================= phase A: Z sweep, m-chunk 256, 16 iterations ================
    {
        for (int u = tid; u < 2048; u += 512) {
            int hl = u >> 10, r = (u >> 2) & 255, w4 = (u & 3) * 4;
            cpa16(BsS + hl * PA_HL + (r * 20 + w4) * 4,
                  (hl ? g_ql : g_qh) + ((size_t)b * NN + r) * 16 + w4);
        }
        asm volatile("cp.async.commit_group;");
    }
    float z0 = 0.f, z1 = 0.f;
    for (int it = 0; it < 16; it++) {
        if (it < 15) {
            int i0n = (it + 1) * 256;
            for (int u = tid; u < 2048; u += 512) {
                int hl = u >> 10, r = (u >> 2) & 255, w4 = (u & 3) * 4;
                cpa16(BsS + ((it + 1) & 1) * PA_BUF + hl * PA_HL + (r * 20 + w4) * 4,
                      (hl ? g_ql : g_qh) + ((size_t)b * NN + i0n + r) * 16 + w4);
            }
        }
        asm volatile("cp.async.commit_group;");
        asm volatile("cp.async.wait_group 1;");
        __syncthreads();
        unsigned qh_b = BsS + (it & 1) * PA_BUF + boffS;
        unsigned ql_b = qh_b + PA_HL;
#pragma unroll
        for (int tp = 0; tp < 16; tp += 2) {
            float d2[2][4];
#pragma unroll
            for (int a = 0; a < 2; a++)
#pragma unroll
                for (int e = 0; e < 4; e++) d2[a][e] = 0.f;
#pragma unroll
            for (int kk2 = 0; kk2 < 2; kk2++) {
                unsigned ro = (unsigned)((m0sA + tp * 8) * 80) + kk2 * 32;
                unsigned bh0, bh1, bh2, bh3, bl0, bl1, bl2, bl3;
                ldsm4(qh_b + ro, bh0, bh1, bh2, bh3);
                ldsm4(ql_b + ro, bl0, bl1, bl2, bl3);
                mma16816(d2[0], ah2[kk2][0], ah2[kk2][1], ah2[kk2][2], ah2[kk2][3], bh0, bh1);
                mma16816(d2[0], ah2[kk2][0], ah2[kk2][1], ah2[kk2][2], ah2[kk2][3], bl0, bl1);
                mma16816(d2[0], al2[kk2][0], al2[kk2][1], al2[kk2][2], al2[kk2][3], bh0, bh1);
                mma16816(d2[1], ah2[kk2][0], ah2[kk2][1], ah2[kk2][2], ah2[kk2][3], bh2, bh3);
                mma16816(d2[1], ah2[kk2][0], ah2[kk2][1], ah2[kk2][2], ah2[kk2][3], bl2, bl3);
                mma16816(d2[1], al2[kk2][0], al2[kk2][1], al2[kk2][2], al2[kk2][3], bh2, bh3);
            }
            z0 += ex2f(d2[0][0]) + ex2f(d2[0][1]) + ex2f(d2[1][0]) + ex2f(d2[1][1]);
            z1 += ex2f(d2[0][2]) + ex2f(d2[0][3]) + ex2f(d2[1][2]) + ex2f(d2[1][3]);
        }
    }
    z0 += __shfl_xor_sync(0xffffffffu, z0, 1);
    z0 += __shfl_xor_sync(0xffffffffu, z0, 2);
    z1 += __shfl_xor_sync(0xffffffffu, z1, 1);
    z1 += __shfl_xor_sync(0xffffffffu, z1, 2);
    if (tg == 0) {
        atomicAdd(&S.zsh[j0s + gid], z0);
        atomicAdd(&S.zsh[j0s + gid + 8], z1);
    }
    asm volatile("cp.async.wait_group 0;");
    __syncthreads();
    float rz0 = 1.f / S.zsh[j0s + gid], rz1 = 1.f / S.zsh[j0s + gid + 8];

    // ================= phase B: single barrier per tile; S(t) + O(t-1); direct AM store ================
    float acc[2][8][4];
#pragma unroll
    for (int a = 0; a < 2; a++)
#pragma unroll
        for (int n = 0; n < 8; n++)
#pragma unroll
            for (int c = 0; c < 4; c++) acc[a][n][c] = 0.f;
    float* AMrow = AM + ((size_t)b * NN + j0) * (size_t)NN;
    int qlf = tid >> 8, qlr = (tid >> 2) & 63, qlw = (tid & 3) * 4;
    {  // prologue: q(0) -> qbuf 0
        cpa16((qlf ? qslS : qshS) + (qlr * 20 + qlw) * 4,
              (qlf ? g_ql : g_qh) + ((size_t)b * NN + qlr) * 16 + qlw);
        asm volatile("cp.async.commit_group;");
    }
    for (int t = 0; t < 64; t++) {
        int m0 = t * 64;
        int qb = t - (t / 3) * 3;             // t % 3
        int qbn = (qb == 2) ? 0 : qb + 1;     // (t+1) % 3
        int vbp3 = (qb == 0) ? 2 : qb - 1;    // (t-1) % 3
        if (t < 63) {  // prefetch q(t+1) -> qbuf (t+1)%3
            const unsigned* qs = (qlf ? g_ql : g_qh) + ((size_t)b * NN + (m0 + 64) + qlr) * 16 + qlw;
            cpa16((qlf ? qslS : qshS) + qbn * QBUF_B + (qlr * 20 + qlw) * 4, qs);
        }
        // v(t) -> vbuf t%3
#pragma unroll
        for (int itv = 0; itv < 4; itv++) {
            int idx = itv * 512 + tid;
            int r = idx >> 3, ch = (idx & 7) * 4;
            cpa16(BsS + qb * VBUF_B + (r * 36 + ch) * 4,
                  vbp + (size_t)r * (NN / 2) + (m0 >> 1) + ch);
        }
        asm volatile("cp.async.commit_group;");
        asm volatile("cp.async.wait_group 1;");
        __syncthreads();  // the ONLY barrier this iteration
        // ---- S-mma(t): reads qbuf t%3 ----
        unsigned qshB = qshS + qb * QBUF_B + boffS;
        unsigned qslB = qslS + qb * QBUF_B + boffS;
        float d[4][4];
#pragma unroll
        for (int tt = 0; tt < 4; tt++)
#pragma unroll
            for (int e = 0; e < 4; e++) d[tt][e] = 0.f;
#pragma unroll
        for (int kk2 = 0; kk2 < 2; kk2++) {
#pragma unroll
            for (int tp = 0; tp < 4; tp += 2) {
                unsigned ro = (unsigned)((m0sB + tp * 8) * 80) + kk2 * 32;
                unsigned bh0, bh1, bh2, bh3, bl0, bl1, bl2, bl3;
                ldsm4(qshB + ro, bh0, bh1, bh2, bh3);
                ldsm4(qslB + ro, bl0, bl1, bl2, bl3);
                mma16816(d[tp], ah2[kk2][0], ah2[kk2][1], ah2[kk2][2], ah2[kk2][3], bh0, bh1);
                mma16816(d[tp], ah2[kk2][0], ah2[kk2][1], ah2[kk2][2], ah2[kk2][3], bl0, bl1);
                mma16816(d[tp], al2[kk2][0], al2[kk2][1], al2[kk2][2], al2[kk2][3], bh0, bh1);
                mma16816(d[tp + 1], ah2[kk2][0], ah2[kk2][1], ah2[kk2][2], ah2[kk2][3], bh2, bh3);
                mma16816(d[tp + 1], ah2[kk2][0], ah2[kk2][1], ah2[kk2][2], ah2[kk2][3], bl2, bl3);
                mma16816(d[tp + 1], al2[kk2][0], al2[kk2][1], al2[kk2][2], al2[kk2][3], bh2, bh3);
            }
        }
        // ---- O-mma(t-1): reads As[(t-1)&1], vbuf (t-1)%3 ----
        if (t > 0) {
            unsigned AsR = AsA + (unsigned)(((t - 1) & 1) * ASBUF_B);
            unsigned BsB = BsS + vbp3 * VBUF_B + boffO;
#pragma unroll
            for (int kk = 0; kk < 4; kk++) {
                unsigned a0[4], a1[4];
                ldsm4(AsR + (unsigned)((wj * 32) * 144 + kk * 32), a0[0], a0[1], a0[2], a0[3]);
                ldsm4(AsR + (unsigned)((wj * 32 + 16) * 144 + kk * 32), a1[0], a1[1], a1[2], a1[3]);
#pragma unroll
                for (int ntp = 0; ntp < 4; ntp++) {
                    unsigned b0a, b1a, b0b, b1b;
                    ldsm4(BsB + (unsigned)((ntp * 16) * 144 + kk * 32), b0a, b1a, b0b, b1b);
                    mma16816(acc[0][2 * ntp], a0[0], a0[1], a0[2], a0[3], b0a, b1a);
                    mma16816(acc[1][2 * ntp], a1[0], a1[1], a1[2], a1[3], b0a, b1a);
                    mma16816(acc[0][2 * ntp + 1], a0[0], a0[1], a0[2], a0[3], b0b, b1b);
                    mma16816(acc[1][2 * ntp + 1], a1[0], a1[1], a1[2], a1[3], b0b, b1b);
                }
            }
        }
        // ---- exp(t): normalize, direct AM store, stage bf16 P into As[t&1] ----
        unsigned* AsW = S.As[t & 1];
#pragma unroll
        for (int tt = 0; tt < 4; tt++) {
            float e0 = ex2f(d[tt][0]) * rz0;
            float e1 = ex2f(d[tt][1]) * rz0;
            float e2 = ex2f(d[tt][2]) * rz1;
            float e3 = ex2f(d[tt][3]) * rz1;
            int col = m0 + m0sB + tt * 8 + 2 * tg;
            *(float2*)&AMrow[(size_t)(j0s + gid) * NN + col] = make_float2(e0, e1);
            *(float2*)&AMrow[(size_t)(j0s + gid + 8) * NN + col] = make_float2(e2, e3);
            AsW[(j0s + gid) * 36 + (m0sB >> 1) + tt * 4 + tg] = bf16bits(e0) | (bf16bits(e1) << 16);
            AsW[(j0s + gid + 8) * 36 + (m0sB >> 1) + tt * 4 + tg] = bf16bits(e2) | (bf16bits(e3) << 16);
        }
    }
    // ---- drain: O(63) reads As[1], vbuf 63%3=0 ----
    asm volatile("cp.async.wait_group 0;");
    __syncthreads();
    {
        unsigned AsR = AsA + (unsigned)ASBUF_B;
        unsigned BsB = BsS + 0 * VBUF_B + boffO;
#pragma unroll
        for (int kk = 0; kk < 4; kk++) {
            unsigned a0[4], a1[4];
            ldsm4(AsR + (unsigned)((wj * 32) * 144 + kk * 32), a0[0], a0[1], a0[2], a0[3]);
            ldsm4(AsR + (unsigned)((wj * 32 + 16) * 144 + kk * 32), a1[0], a1[1], a1[2], a1[3]);
#pragma unroll
            for (int ntp = 0; ntp < 4; ntp++) {
                unsigned b0a, b1a, b0b, b1b;
                ldsm4(BsB + (unsigned)((ntp * 16) * 144 + kk * 32), b0a, b1a, b0b, b1b);
                mma16816(acc[0][2 * ntp], a0[0], a0[1], a0[2], a0[3], b0a, b1a);
                mma16816(acc[1][2 * ntp], a1[0], a1[1], a1[2], a1[3], b0a, b1a);
                mma16816(acc[0][2 * ntp + 1], a0[0], a0[1], a0[2], a0[3], b0b, b1b);
                mma16816(acc[1][2 * ntp + 1], a1[0], a1[1], a1[2], a1[3], b0b, b1b);
            }
        }
    }
    __syncthreads();
    // ---- epilogue: out = x + gamma*o; 4 phases of 32 j rows ----
    float gma = __ldg(gptr);
    float* fBs = (float*)S.Bs[0];  // 32 x 256 fp32
    int ec = tid & 255, ejh = tid >> 8;
    for (int h = 0; h < 4; h++) {
        if (wj == h) {
#pragma unroll
            for (int jt = 0; jt < 2; jt++)
#pragma unroll
                for (int nt = 0; nt < 8; nt++) {
                    int rr = jt * 16 + gid;
                    int cc2 = wc * 64 + nt * 8 + tg * 2;
                    fBs[rr * 256 + cc2]           = acc[jt][nt][0];
                    fBs[rr * 256 + cc2 + 1]       = acc[jt][nt][1];
                    fBs[(rr + 8) * 256 + cc2]     = acc[jt][nt][2];
                    fBs[(rr + 8) * 256 + cc2 + 1] = acc[jt][nt][3];
                }
        }
        __syncthreads();
        const float* xrow = x + ((size_t)b * CC + ec) * NN + j0 + h * 32 + ejh * 16;
        float* orow = outp + ((size_t)b * CC + ec) * NN + j0 + h * 32 + ejh * 16;
#pragma unroll
        for (int jq = 0; jq < 4; jq++) {
            float4 o;
            o.x = fBs[(ejh * 16 + jq * 4 + 0) * 256 + ec];
            o.y = fBs[(ejh * 16 + jq * 4 + 1) * 256 + ec];
            o.z = fBs[(ejh * 16 + jq * 4 + 2) * 256 + ec];
            o.w = fBs[(ejh * 16 + jq * 4 + 3) * 256 + ec];
            float4 xr = *(const float4*)(xrow + jq * 4);
            float4 res = {xr.x + gma * o.x, xr.y + gma * o.y, xr.z + gma * o.z, xr.w + gma * o.w};
            *(float4*)(orow + jq * 4) = res;
        }
        __syncthreads();
    }
}

// ---------------- launch ----------------
extern "C" void kernel_launch(void* const* d_in, const int* in_sizes, int n_in,
                              void* d_out, int out_size) {
    const float* x  = (const float*)d_in[0];
    const float* Wq = (const float*)d_in[1];
    const float* bq = (const float*)d_in[2];
    const float* Wk = (const float*)d_in[3];
    const float* bk = (const float*)d_in[4];
    const float* Wv = (const float*)d_in[5];
    const float* bv = (const float*)d_in[6];
    const float* gm = (const float*)d_in[7];
    float* outp = (float*)d_out;
    float* AM = outp + (size_t)BN * CC * 64 * 64;

    cudaFuncSetAttribute(k_o7, cudaFuncAttributeMaxDynamicSharedMemorySize,
                         (int)sizeof(Ko7Smem));

    k_proj<<<dim3(128, BN), 256>>>(x, Wq, bq, Wk, bk, Wv, bv);
    k_o7<<<dim3(32, BN), 512, sizeof(Ko7Smem)>>>(AM, x, gm, outp);
}

// round 16
// speedup vs baseline: 1.0613x; 1.0613x over previous
#include <cuda_runtime.h>
#include <cstdint>

#define BN 4
#define CC 256
#define NN 4096
#define LOG2E 1.4426950408889634f

// ---------------- scratch ----------------
__device__ unsigned g_qh[BN * NN * 16];         // [b][n][cw] hi bf16 pair (c even/odd packed)
__device__ unsigned g_ql[BN * NN * 16];         // lo residual
__device__ unsigned g_kh[BN * NN * 16];         // k pre-scaled by log2(e)
__device__ unsigned g_kl[BN * NN * 16];
__device__ unsigned g_vtp[BN * CC * (NN / 2)]; // [b][c][m2] = pack(v[c][2m2], v[c][2m2+1])

__device__ __forceinline__ unsigned bf16bits(float f) {
    unsigned u = __float_as_uint(f);
    return (u + 0x7fffu + ((u >> 16) & 1u)) >> 16;
}

__device__ __forceinline__ unsigned sptr(const void* p) {
    unsigned a;
    asm("{ .reg .u64 t; cvta.to.shared.u64 t, %1; cvt.u32.u64 %0, t; }" : "=r"(a) : "l"(p));
    return a;
}

__device__ __forceinline__ float ex2f(float x) {
    float y;
    asm("ex2.approx.f32 %0, %1;" : "=f"(y) : "f"(x));
    return y;
}

__device__ __forceinline__ void ldsm4(unsigned a, unsigned& r0, unsigned& r1, unsigned& r2, unsigned& r3) {
    asm volatile("ldmatrix.sync.aligned.m8n8.x4.shared.b16 {%0,%1,%2,%3}, [%4];"
                 : "=r"(r0), "=r"(r1), "=r"(r2), "=r"(r3) : "r"(a));
}

__device__ __forceinline__ void mma16816(float* d, unsigned a0, unsigned a1, unsigned a2, unsigned a3,
                                         unsigned b0, unsigned b1) {
    asm volatile(
        "mma.sync.aligned.m16n8k16.row.col.f32.bf16.bf16.f32 "
        "{%0,%1,%2,%3}, {%4,%5,%6,%7}, {%8,%9}, {%0,%1,%2,%3};\n"
        : "+f"(d[0]), "+f"(d[1]), "+f"(d[2]), "+f"(d[3])
        : "r"(a0), "r"(a1), "r"(a2), "r"(a3), "r"(b0), "r"(b1));
}

__device__ __forceinline__ void cpa16(unsigned dst, const void* src) {
    asm volatile("cp.async.cg.shared.global [%0], [%1], 16;" :: "r"(dst), "l"(src));
}

// ---------------- K1a: q,k projections (R14-validated, at FMA floor) ----------------
__global__ void __launch_bounds__(256) k_qk(const float* __restrict__ x,
                                            const float* __restrict__ Wq, const float* __restrict__ bq,
                                            const float* __restrict__ Wk, const float* __restrict__ bk) {
    __shared__ float Ws[64][33];
    __shared__ float Xs[32][68];
    int b = blockIdx.y;
    int n0 = blockIdx.x * 64;
    int tid = threadIdx.x;
    const float* xb = x + (size_t)b * CC * NN;
    float acc[4][4];
#pragma unroll
    for (int i = 0; i < 4; i++)
#pragma unroll
        for (int j = 0; j < 4; j++) acc[i][j] = 0.f;
    int tr = tid >> 4, tn = tid & 15;
    for (int k0 = 0; k0 < CC; k0 += 32) {
        for (int i = tid; i < 64 * 32; i += 256) {
            int r = i >> 5, kk = i & 31;
            Ws[r][kk] = (r < 32) ? Wq[r * CC + k0 + kk] : Wk[(r - 32) * CC + k0 + kk];
        }
        {
            int kk = tid >> 3, nn = (tid & 7) * 8;
            *(float4*)&Xs[kk][nn] = *(const float4*)&xb[(size_t)(k0 + kk) * NN + n0 + nn];
            *(float4*)&Xs[kk][nn + 4] = *(const float4*)&xb[(size_t)(k0 + kk) * NN + n0 + nn + 4];
        }
        __syncthreads();
#pragma unroll
        for (int kk = 0; kk < 32; kk++) {
            float wf[4], xf[4];
#pragma unroll
            for (int i = 0; i < 4; i++) wf[i] = Ws[tr * 4 + i][kk];
            *(float4*)&xf[0] = *(float4*)&Xs[kk][tn * 4];
#pragma unroll
            for (int i = 0; i < 4; i++)
#pragma unroll
                for (int j = 0; j < 4; j++) acc[i][j] += wf[i] * xf[j];
        }
        __syncthreads();
    }
#pragma unroll
    for (int i = 0; i < 4; i++) {
        int r = tr * 4 + i;
        float bias = (r < 32) ? bq[r] : bk[r - 32];
        float scale = (r < 32) ? 1.f : LOG2E;  // fold log2e into k so exp(s) = ex2(s')
#pragma unroll
        for (int j = 0; j < 4; j++) acc[i][j] = (acc[i][j] + bias) * scale;
    }
    unsigned hw[2][4], lw[2][4];
#pragma unroll
    for (int p = 0; p < 2; p++)
#pragma unroll
        for (int j = 0; j < 4; j++) {
            float a0 = acc[2 * p][j], a1 = acc[2 * p + 1][j];
            unsigned h0 = bf16bits(a0);
            unsigned h1 = bf16bits(a1);
            float f0 = __uint_as_float(h0 << 16);
            float f1 = __uint_as_float(h1 << 16);
            unsigned l0 = bf16bits(a0 - f0);
            unsigned l1 = bf16bits(a1 - f1);
            hw[p][j] = h0 | (h1 << 16);
            lw[p][j] = l0 | (l1 << 16);
        }
    unsigned* st = (unsigned*)&Xs[0][0];  // 64 x 17 staging
    bool isq = (tr < 8);
    int cw0 = (isq ? tr : tr - 8) * 2;
    for (int ph = 0; ph < 4; ph++) {
        bool mine = (ph < 2) ? isq : !isq;
        bool lo = (ph & 1);
        __syncthreads();
        if (mine) {
#pragma unroll
            for (int p = 0; p < 2; p++)
#pragma unroll
                for (int j = 0; j < 4; j++)
                    st[(tn * 4 + j) * 17 + cw0 + p] = lo ? lw[p][j] : hw[p][j];
        }
        __syncthreads();
        unsigned* dst = (ph == 0 ? g_qh : ph == 1 ? g_ql : ph == 2 ? g_kh : g_kl)
                        + ((size_t)b * NN + n0) * 16;
        int row = tid >> 2, w0 = (tid & 3) * 4;
        unsigned t0 = st[row * 17 + w0 + 0], t1 = st[row * 17 + w0 + 1];
        unsigned t2 = st[row * 17 + w0 + 2], t3 = st[row * 17 + w0 + 3];
        *(uint4*)&dst[row * 16 + w0] = make_uint4(t0, t1, t2, t3);
    }
}

// ---------------- K1b: v projection; 8c x 8n accs, n-tile 64 (R14-validated) ----------------
__global__ void __launch_bounds__(256) k_v(const float* __restrict__ x,
                                           const float* __restrict__ Wv, const float* __restrict__ bv) {
    __shared__ float Ws[256][33];
    __shared__ float Xs[32][68];
    int nb = blockIdx.x, b = blockIdx.y;
    int n0 = nb * 64;
    int tid = threadIdx.x;
    const float* xb = x + (size_t)b * CC * NN;
    float acc[8][8];
#pragma unroll
    for (int i = 0; i < 8; i++)
#pragma unroll
        for (int j = 0; j < 8; j++) acc[i][j] = 0.f;
    int tr = tid >> 3, tc = tid & 7;  // 8 c-rows x 8 n-cols per thread
    for (int k0 = 0; k0 < CC; k0 += 32) {
        {
            const float4* src = (const float4*)&Wv[(size_t)tid * CC + k0];
#pragma unroll
            for (int q = 0; q < 8; q++) {
                float4 w4 = src[q];
                Ws[tid][q * 4 + 0] = w4.x;
                Ws[tid][q * 4 + 1] = w4.y;
                Ws[tid][q * 4 + 2] = w4.z;
                Ws[tid][q * 4 + 3] = w4.w;
            }
        }
        {
            int kk = tid >> 3, nn = (tid & 7) * 8;
            *(float4*)&Xs[kk][nn] = *(const float4*)&xb[(size_t)(k0 + kk) * NN + n0 + nn];
            *(float4*)&Xs[kk][nn + 4] = *(const float4*)&xb[(size_t)(k0 + kk) * NN + n0 + nn + 4];
        }
        __syncthreads();
#pragma unroll
        for (int kk = 0; kk < 32; kk++) {
            float xf[8];
            *(float4*)&xf[0] = *(float4*)&Xs[kk][tc * 8];
            *(float4*)&xf[4] = *(float4*)&Xs[kk][tc * 8 + 4];
#pragma unroll
            for (int i = 0; i < 8; i++) {
                float wv = Ws[tr * 8 + i][kk];
#pragma unroll
                for (int j = 0; j < 8; j++) acc[i][j] += wv * xf[j];
            }
        }
        __syncthreads();
    }
#pragma unroll
    for (int i = 0; i < 8; i++) {
        int c = tr * 8 + i;
        float bias = bv[c];
        unsigned w[4];
#pragma unroll
        for (int p = 0; p < 4; p++)
            w[p] = bf16bits(acc[i][2 * p] + bias) | (bf16bits(acc[i][2 * p + 1] + bias) << 16);
        *(uint4*)&g_vtp[((size_t)b * CC + c) * (NN / 2) + (n0 >> 1) + tc * 4] =
            make_uint4(w[0], w[1], w[2], w[3]);
    }
}

// ---------------- KO8: j=128/512thr; single-barrier phase-B; O-stage B-fragment pipeline ----------------
struct Ko8Smem {
    unsigned ksh[128 * 20];
    unsigned ksl[128 * 20];
    unsigned qsh[3][64 * 20];
    unsigned qsl[3][64 * 20];
    unsigned As[2][128 * 36];  // bf16 P tile, double buffered
    unsigned Bs[3][256 * 36];  // v chunks triple buffered; phase-A q stream; epilogue fp32 staging
    float zsh[128];
};
#define QBUF_B (64 * 20 * 4)
#define VBUF_B (256 * 36 * 4)
#define ASBUF_B (128 * 36 * 4)
#define PA_HL  (256 * 20 * 4)
#define PA_BUF (2 * PA_HL)

__global__ void __launch_bounds__(512) k_o8(float* __restrict__ AM, const float* __restrict__ x,
                                            const float* __restrict__ gptr, float* __restrict__ outp) {
    extern __shared__ Ko8Smem s8[];
    Ko8Smem& S = s8[0];
    int jb = blockIdx.x, b = blockIdx.y;
    int j0 = jb * 128;
    int tid = threadIdx.x;
    if (tid < 128) S.zsh[tid] = 0.f;
    // K tiles once
    for (int u = tid; u < 1024; u += 512) {
        int bufl = u >> 9, r = (u >> 2) & 127, w = (u & 3) * 4;
        const unsigned* src = (bufl ? g_kl : g_kh) + ((size_t)b * NN + j0 + r) * 16 + w;
        unsigned* dst = (bufl ? S.ksl : S.ksh) + r * 20 + w;
        *(uint4*)dst = *(const uint4*)src;
    }
    __syncthreads();

    int warp = tid >> 5, lane = tid & 31, gid = lane >> 2, tg = lane & 3;
    int j0s = (warp & 7) * 16;
    int m0sB = (warp >> 3) * 32, m0sA = (warp >> 3) * 128;
    int wj = warp >> 2, wc = warp & 3;
    unsigned aoffS = ((j0s + (lane & 15)) * 20 + ((lane >> 4) << 2)) * 4;
    unsigned kshA = sptr(S.ksh) + aoffS, kslA = sptr(S.ksl) + aoffS;
    unsigned boffS = (((lane & 7) + ((lane & 16) >> 1)) * 20 + ((lane & 8) >> 1)) * 4;
    unsigned AsA = sptr(S.As[0]) + ((lane & 15) * 36 + ((lane >> 4) << 2)) * 4;
    unsigned boffO = ((((lane & 7) + ((lane & 16) >> 1)) + wc * 64) * 36 + ((lane & 8) >> 1)) * 4;
    unsigned qshS = sptr(S.qsh[0]), qslS = sptr(S.qsl[0]), BsS = sptr(S.Bs[0]);
    const unsigned* vbp = g_vtp + (size_t)b * CC * (NN / 2);

    // hoisted k A-fragments (loop-invariant across BOTH phases)
    unsigned ah2[2][4], al2[2][4];
    ldsm4(kshA + 0, ah2[0][0], ah2[0][1], ah2[0][2], ah2[0][3]);
    ldsm4(kshA + 32, ah2[1][0], ah2[1][1], ah2[1][2], ah2[1][3]);
    ldsm4(kslA + 0, al2[0][0], al2[0][1], al2[0][2], al2[0][3]);
    ldsm4(kslA + 32, al2[1][0], al2[1][1], al2[1][2], al2[1][3]);

    // ================= phase A: Z sweep, m-chunk 256, 16 iterations ================
    {
        for (int u = tid; u < 2048; u += 512) {
            int hl = u >> 10, r = (u >> 2) & 255, w4 = (u & 3) * 4;
            cpa16(BsS + hl * PA_HL + (r * 20 + w4) * 4,
                  (hl ? g_ql : g_qh) + ((size_t)b * NN + r) * 16 + w4);
        }
        asm volatile("cp.async.commit_group;");
    }
    float z0 = 0.f, z1 = 0.f;
    for (int it = 0; it < 16; it++) {
        if (it < 15) {
            int i0n = (it + 1) * 256;
            for (int u = tid; u < 2048; u += 512) {
                int hl = u >> 10, r = (u >> 2) & 255, w4 = (u & 3) * 4;
                cpa16(BsS + ((it + 1) & 1) * PA_BUF + hl * PA_HL + (r * 20 + w4) * 4,
                      (hl ? g_ql : g_qh) + ((size_t)b * NN + i0n + r) * 16 + w4);
            }
        }
        asm volatile("cp.async.commit_group;");
        asm volatile("cp.async.wait_group 1;");
        __syncthreads();
        unsigned qh_b = BsS + (it & 1) * PA_BUF + boffS;
        unsigned ql_b = qh_b + PA_HL;
#pragma unroll
        for (int tp = 0; tp < 16; tp += 2) {
            float d2[2][4];
#pragma unroll
            for (int a = 0; a < 2; a++)
#pragma unroll
                for (int e = 0; e < 4; e++) d2[a][e] = 0.f;
#pragma unroll
            for (int kk2 = 0; kk2 < 2; kk2++) {
                unsigned ro = (unsigned)((m0sA + tp * 8) * 80) + kk2 * 32;
                unsigned bh0, bh1, bh2, bh3, bl0, bl1, bl2, bl3;
                ldsm4(qh_b + ro, bh0, bh1, bh2, bh3);
                ldsm4(ql_b + ro, bl0, bl1, bl2, bl3);
                mma16816(d2[0], ah2[kk2][0], ah2[kk2][1], ah2[kk2][2], ah2[kk2][3], bh0, bh1);
                mma16816(d2[0], ah2[kk2][0], ah2[kk2][1], ah2[kk2][2], ah2[kk2][3], bl0, bl1);
                mma16816(d2[0], al2[kk2][0], al2[kk2][1], al2[kk2][2], al2[kk2][3], bh0, bh1);
                mma16816(d2[1], ah2[kk2][0], ah2[kk2][1], ah2[kk2][2], ah2[kk2][3], bh2, bh3);
                mma16816(d2[1], ah2[kk2][0], ah2[kk2][1], ah2[kk2][2], ah2[kk2][3], bl2, bl3);
                mma16816(d2[1], al2[kk2][0], al2[kk2][1], al2[kk2][2], al2[kk2][3], bh2, bh3);
            }
            z0 += ex2f(d2[0][0]) + ex2f(d2[0][1]) + ex2f(d2[1][0]) + ex2f(d2[1][1]);
            z1 += ex2f(d2[0][2]) + ex2f(d2[0][3]) + ex2f(d2[1][2]) + ex2f(d2[1][3]);
        }
    }
    z0 += __shfl_xor_sync(0xffffffffu, z0, 1);
    z0 += __shfl_xor_sync(0xffffffffu, z0, 2);
    z1 += __shfl_xor_sync(0xffffffffu, z1, 1);
    z1 += __shfl_xor_sync(0xffffffffu, z1, 2);
    if (tg == 0) {
        atomicAdd(&S.zsh[j0s + gid], z0);
        atomicAdd(&S.zsh[j0s + gid + 8], z1);
    }
    asm volatile("cp.async.wait_group 0;");
    __syncthreads();
    float rz0 = 1.f / S.zsh[j0s + gid], rz1 = 1.f / S.zsh[j0s + gid + 8];

    // ================= phase B: single barrier per tile; S(t) + O(t-1); direct AM store ================
    float acc[2][8][4];
#pragma unroll
    for (int a = 0; a < 2; a++)
#pragma unroll
        for (int n = 0; n < 8; n++)
#pragma unroll
            for (int c = 0; c < 4; c++) acc[a][n][c] = 0.f;
    float* AMrow = AM + ((size_t)b * NN + j0) * (size_t)NN;
    int qlf = tid >> 8, qlr = (tid >> 2) & 63, qlw = (tid & 3) * 4;
    {  // prologue: q(0) -> qbuf 0
        cpa16((qlf ? qslS : qshS) + (qlr * 20 + qlw) * 4,
              (qlf ? g_ql : g_qh) + ((size_t)b * NN + qlr) * 16 + qlw);
        asm volatile("cp.async.commit_group;");
    }
    for (int t = 0; t < 64; t++) {
        int m0 = t * 64;
        int qb = t - (t / 3) * 3;             // t % 3
        int qbn = (qb == 2) ? 0 : qb + 1;     // (t+1) % 3
        int vbp3 = (qb == 0) ? 2 : qb - 1;    // (t-1) % 3
        if (t < 63) {  // prefetch q(t+1) -> qbuf (t+1)%3
            const unsigned* qs = (qlf ? g_ql : g_qh) + ((size_t)b * NN + (m0 + 64) + qlr) * 16 + qlw;
            cpa16((qlf ? qslS : qshS) + qbn * QBUF_B + (qlr * 20 + qlw) * 4, qs);
        }
        // v(t) -> vbuf t%3
#pragma unroll
        for (int itv = 0; itv < 4; itv++) {
            int idx = itv * 512 + tid;
            int r = idx >> 3, ch = (idx & 7) * 4;
            cpa16(BsS + qb * VBUF_B + (r * 36 + ch) * 4,
                  vbp + (size_t)r * (NN / 2) + (m0 >> 1) + ch);
        }
        asm volatile("cp.async.commit_group;");
        asm volatile("cp.async.wait_group 1;");
        __syncthreads();  // the ONLY barrier this iteration
        // ---- S-mma(t): reads qbuf t%3 ----
        unsigned qshB = qshS + qb * QBUF_B + boffS;
        unsigned qslB = qslS + qb * QBUF_B + boffS;
        float d[4][4];
#pragma unroll
        for (int tt = 0; tt < 4; tt++)
#pragma unroll
            for (int e = 0; e < 4; e++) d[tt][e] = 0.f;
#pragma unroll
        for (int kk2 = 0; kk2 < 2; kk2++) {
#pragma unroll
            for (int tp = 0; tp < 4; tp += 2) {
                unsigned ro = (unsigned)((m0sB + tp * 8) * 80) + kk2 * 32;
                unsigned bh0, bh1, bh2, bh3, bl0, bl1, bl2, bl3;
                ldsm4(qshB + ro, bh0, bh1, bh2, bh3);
                ldsm4(qslB + ro, bl0, bl1, bl2, bl3);
                mma16816(d[tp], ah2[kk2][0], ah2[kk2][1], ah2[kk2][2], ah2[kk2][3], bh0, bh1);
                mma16816(d[tp], ah2[kk2][0], ah2[kk2][1], ah2[kk2][2], ah2[kk2][3], bl0, bl1);
                mma16816(d[tp], al2[kk2][0], al2[kk2][1], al2[kk2][2], al2[kk2][3], bh0, bh1);
                mma16816(d[tp + 1], ah2[kk2][0], ah2[kk2][1], ah2[kk2][2], ah2[kk2][3], bh2, bh3);
                mma16816(d[tp + 1], ah2[kk2][0], ah2[kk2][1], ah2[kk2][2], ah2[kk2][3], bl2, bl3);
                mma16816(d[tp + 1], al2[kk2][0], al2[kk2][1], al2[kk2][2], al2[kk2][3], bh2, bh3);
            }
        }
        // ---- O-mma(t-1): depth-1 B-fragment pipeline (hide ldsm latency under mma groups) ----
        if (t > 0) {
            unsigned AsR = AsA + (unsigned)(((t - 1) & 1) * ASBUF_B);
            unsigned BsB = BsS + vbp3 * VBUF_B + boffO;
#pragma unroll
            for (int kk = 0; kk < 4; kk++) {
                unsigned a0[4], a1[4];
                ldsm4(AsR + (unsigned)((wj * 32) * 144 + kk * 32), a0[0], a0[1], a0[2], a0[3]);
                ldsm4(AsR + (unsigned)((wj * 32 + 16) * 144 + kk * 32), a1[0], a1[1], a1[2], a1[3]);
                unsigned bc0, bc1, bc2, bc3;
                ldsm4(BsB + (unsigned)(kk * 32), bc0, bc1, bc2, bc3);
#pragma unroll
                for (int ntp = 0; ntp < 4; ntp++) {
                    unsigned bn0 = 0, bn1 = 0, bn2 = 0, bn3 = 0;
                    if (ntp < 3)
                        ldsm4(BsB + (unsigned)(((ntp + 1) * 16) * 144 + kk * 32), bn0, bn1, bn2, bn3);
                    mma16816(acc[0][2 * ntp], a0[0], a0[1], a0[2], a0[3], bc0, bc1);
                    mma16816(acc[1][2 * ntp], a1[0], a1[1], a1[2], a1[3], bc0, bc1);
                    mma16816(acc[0][2 * ntp + 1], a0[0], a0[1], a0[2], a0[3], bc2, bc3);
                    mma16816(acc[1][2 * ntp + 1], a1[0], a1[1], a1[2], a1[3], bc2, bc3);
                    bc0 = bn0; bc1 = bn1; bc2 = bn2; bc3 = bn3;
                }
            }
        }
        // ---- exp(t): normalize, direct AM store, stage bf16 P into As[t&1] ----
        unsigned* AsW = S.As[t & 1];
#pragma unroll
        for (int tt = 0; tt < 4; tt++) {
            float e0 = ex2f(d[tt][0]) * rz0;
            float e1 = ex2f(d[tt][1]) * rz0;
            float e2 = ex2f(d[tt][2]) * rz1;
            float e3 = ex2f(d[tt][3]) * rz1;
            int col = m0 + m0sB + tt * 8 + 2 * tg;
            *(float2*)&AMrow[(size_t)(j0s + gid) * NN + col] = make_float2(e0, e1);
            *(float2*)&AMrow[(size_t)(j0s + gid + 8) * NN + col] = make_float2(e2, e3);
            AsW[(j0s + gid) * 36 + (m0sB >> 1) + tt * 4 + tg] = bf16bits(e0) | (bf16bits(e1) << 16);
            AsW[(j0s + gid + 8) * 36 + (m0sB >> 1) + tt * 4 + tg] = bf16bits(e2) | (bf16bits(e3) << 16);
        }
    }
    // ---- drain: O(63) reads As[1], vbuf 63%3=0 ----
    asm volatile("cp.async.wait_group 0;");
    __syncthreads();
    {
        unsigned AsR = AsA + (unsigned)ASBUF_B;
        unsigned BsB = BsS + 0 * VBUF_B + boffO;
#pragma unroll
        for (int kk = 0; kk < 4; kk++) {
            unsigned a0[4], a1[4];
            ldsm4(AsR + (unsigned)((wj * 32) * 144 + kk * 32), a0[0], a0[1], a0[2], a0[3]);
            ldsm4(AsR + (unsigned)((wj * 32 + 16) * 144 + kk * 32), a1[0], a1[1], a1[2], a1[3]);
#pragma unroll
            for (int ntp = 0; ntp < 4; ntp++) {
                unsigned b0a, b1a, b0b, b1b;
                ldsm4(BsB + (unsigned)((ntp * 16) * 144 + kk * 32), b0a, b1a, b0b, b1b);
                mma16816(acc[0][2 * ntp], a0[0], a0[1], a0[2], a0[3], b0a, b1a);
                mma16816(acc[1][2 * ntp], a1[0], a1[1], a1[2], a1[3], b0a, b1a);
                mma16816(acc[0][2 * ntp + 1], a0[0], a0[1], a0[2], a0[3], b0b, b1b);
                mma16816(acc[1][2 * ntp + 1], a1[0], a1[1], a1[2], a1[3], b0b, b1b);
            }
        }
    }
    __syncthreads();
    // ---- epilogue: out = x + gamma*o; 4 phases of 32 j rows ----
    float gma = __ldg(gptr);
    float* fBs = (float*)S.Bs[0];  // 32 x 256 fp32
    int ec = tid & 255, ejh = tid >> 8;
    for (int h = 0; h < 4; h++) {
        if (wj == h) {
#pragma unroll
            for (int jt = 0; jt < 2; jt++)
#pragma unroll
                for (int nt = 0; nt < 8; nt++) {
                    int rr = jt * 16 + gid;
                    int cc2 = wc * 64 + nt * 8 + tg * 2;
                    fBs[rr * 256 + cc2]           = acc[jt][nt][0];
                    fBs[rr * 256 + cc2 + 1]       = acc[jt][nt][1];
                    fBs[(rr + 8) * 256 + cc2]     = acc[jt][nt][2];
                    fBs[(rr + 8) * 256 + cc2 + 1] = acc[jt][nt][3];
                }
        }
        __syncthreads();
        const float* xrow = x + ((size_t)b * CC + ec) * NN + j0 + h * 32 + ejh * 16;
        float* orow = outp + ((size_t)b * CC + ec) * NN + j0 + h * 32 + ejh * 16;
#pragma unroll
        for (int jq = 0; jq < 4; jq++) {
            float4 o;
            o.x = fBs[(ejh * 16 + jq * 4 + 0) * 256 + ec];
            o.y = fBs[(ejh * 16 + jq * 4 + 1) * 256 + ec];
            o.z = fBs[(ejh * 16 + jq * 4 + 2) * 256 + ec];
            o.w = fBs[(ejh * 16 + jq * 4 + 3) * 256 + ec];
            float4 xr = *(const float4*)(xrow + jq * 4);
            float4 res = {xr.x + gma * o.x, xr.y + gma * o.y, xr.z + gma * o.z, xr.w + gma * o.w};
            *(float4*)(orow + jq * 4) = res;
        }
        __syncthreads();
    }
}

// ---------------- launch ----------------
extern "C" void kernel_launch(void* const* d_in, const int* in_sizes, int n_in,
                              void* d_out, int out_size) {
    const float* x  = (const float*)d_in[0];
    const float* Wq = (const float*)d_in[1];
    const float* bq = (const float*)d_in[2];
    const float* Wk = (const float*)d_in[3];
    const float* bk = (const float*)d_in[4];
    const float* Wv = (const float*)d_in[5];
    const float* bv = (const float*)d_in[6];
    const float* gm = (const float*)d_in[7];
    float* outp = (float*)d_out;
    float* AM = outp + (size_t)BN * CC * 64 * 64;

    cudaFuncSetAttribute(k_o8, cudaFuncAttributeMaxDynamicSharedMemorySize,
                         (int)sizeof(Ko8Smem));

    k_qk<<<dim3(64, BN), 256>>>(x, Wq, bq, Wk, bk);
    k_v<<<dim3(64, BN), 256>>>(x, Wv, bv);
    k_o8<<<dim3(32, BN), 512, sizeof(Ko8Smem)>>>(AM, x, gm, outp);
}

// round 17
// speedup vs baseline: 1.1462x; 1.0800x over previous
#include <cuda_runtime.h>
#include <cstdint>

#define BN 4
#define CC 256
#define NN 4096
#define LOG2E 1.4426950408889634f

// ---------------- scratch ----------------
__device__ unsigned g_qh[BN * NN * 16];         // [b][n][cw] hi bf16 pair (c even/odd packed)
__device__ unsigned g_ql[BN * NN * 16];         // lo residual
__device__ unsigned g_kh[BN * NN * 16];         // k pre-scaled by log2(e)
__device__ unsigned g_kl[BN * NN * 16];
__device__ unsigned g_vtp[BN * CC * (NN / 2)]; // [b][c][m2] = pack(v[c][2m2], v[c][2m2+1])

__device__ __forceinline__ unsigned bf16bits(float f) {
    unsigned u = __float_as_uint(f);
    return (u + 0x7fffu + ((u >> 16) & 1u)) >> 16;
}

__device__ __forceinline__ unsigned sptr(const void* p) {
    unsigned a;
    asm("{ .reg .u64 t; cvta.to.shared.u64 t, %1; cvt.u32.u64 %0, t; }" : "=r"(a) : "l"(p));
    return a;
}

__device__ __forceinline__ float ex2f(float x) {
    float y;
    asm("ex2.approx.f32 %0, %1;" : "=f"(y) : "f"(x));
    return y;
}

__device__ __forceinline__ void ldsm4(unsigned a, unsigned& r0, unsigned& r1, unsigned& r2, unsigned& r3) {
    asm volatile("ldmatrix.sync.aligned.m8n8.x4.shared.b16 {%0,%1,%2,%3}, [%4];"
                 : "=r"(r0), "=r"(r1), "=r"(r2), "=r"(r3) : "r"(a));
}

__device__ __forceinline__ void mma16816(float* d, unsigned a0, unsigned a1, unsigned a2, unsigned a3,
                                         unsigned b0, unsigned b1) {
    asm volatile(
        "mma.sync.aligned.m16n8k16.row.col.f32.bf16.bf16.f32 "
        "{%0,%1,%2,%3}, {%4,%5,%6,%7}, {%8,%9}, {%0,%1,%2,%3};\n"
        : "+f"(d[0]), "+f"(d[1]), "+f"(d[2]), "+f"(d[3])
        : "r"(a0), "r"(a1), "r"(a2), "r"(a3), "r"(b0), "r"(b1));
}

__device__ __forceinline__ void cpa16(unsigned dst, const void* src) {
    asm volatile("cp.async.cg.shared.global [%0], [%1], 16;" :: "r"(dst), "l"(src));
}

// ---------------- K1a: q,k projections (R14-validated, at FMA floor) ----------------
__global__ void __launch_bounds__(256) k_qk(const float* __restrict__ x,
                                            const float* __restrict__ Wq, const float* __restrict__ bq,
                                            const float* __restrict__ Wk, const float* __restrict__ bk) {
    __shared__ float Ws[64][33];
    __shared__ float Xs[32][68];
    int b = blockIdx.y;
    int n0 = blockIdx.x * 64;
    int tid = threadIdx.x;
    const float* xb = x + (size_t)b * CC * NN;
    float acc[4][4];
#pragma unroll
    for (int i = 0; i < 4; i++)
#pragma unroll
        for (int j = 0; j < 4; j++) acc[i][j] = 0.f;
    int tr = tid >> 4, tn = tid & 15;
    for (int k0 = 0; k0 < CC; k0 += 32) {
        for (int i = tid; i < 64 * 32; i += 256) {
            int r = i >> 5, kk = i & 31;
            Ws[r][kk] = (r < 32) ? Wq[r * CC + k0 + kk] : Wk[(r - 32) * CC + k0 + kk];
        }
        {
            int kk = tid >> 3, nn = (tid & 7) * 8;
            *(float4*)&Xs[kk][nn] = *(const float4*)&xb[(size_t)(k0 + kk) * NN + n0 + nn];
            *(float4*)&Xs[kk][nn + 4] = *(const float4*)&xb[(size_t)(k0 + kk) * NN + n0 + nn + 4];
        }
        __syncthreads();
#pragma unroll
        for (int kk = 0; kk < 32; kk++) {
            float wf[4], xf[4];
#pragma unroll
            for (int i = 0; i < 4; i++) wf[i] = Ws[tr * 4 + i][kk];
            *(float4*)&xf[0] = *(float4*)&Xs[kk][tn * 4];
#pragma unroll
            for (int i = 0; i < 4; i++)
#pragma unroll
                for (int j = 0; j < 4; j++) acc[i][j] += wf[i] * xf[j];
        }
        __syncthreads();
    }
#pragma unroll
    for (int i = 0; i < 4; i++) {
        int r = tr * 4 + i;
        float bias = (r < 32) ? bq[r] : bk[r - 32];
        float scale = (r < 32) ? 1.f : LOG2E;  // fold log2e into k so exp(s) = ex2(s')
#pragma unroll
        for (int j = 0; j < 4; j++) acc[i][j] = (acc[i][j] + bias) * scale;
    }
    unsigned hw[2][4], lw[2][4];
#pragma unroll
    for (int p = 0; p < 2; p++)
#pragma unroll
        for (int j = 0; j < 4; j++) {
            float a0 = acc[2 * p][j], a1 = acc[2 * p + 1][j];
            unsigned h0 = bf16bits(a0);
            unsigned h1 = bf16bits(a1);
            float f0 = __uint_as_float(h0 << 16);
            float f1 = __uint_as_float(h1 << 16);
            unsigned l0 = bf16bits(a0 - f0);
            unsigned l1 = bf16bits(a1 - f1);
            hw[p][j] = h0 | (h1 << 16);
            lw[p][j] = l0 | (l1 << 16);
        }
    unsigned* st = (unsigned*)&Xs[0][0];  // 64 x 17 staging
    bool isq = (tr < 8);
    int cw0 = (isq ? tr : tr - 8) * 2;
    for (int ph = 0; ph < 4; ph++) {
        bool mine = (ph < 2) ? isq : !isq;
        bool lo = (ph & 1);
        __syncthreads();
        if (mine) {
#pragma unroll
            for (int p = 0; p < 2; p++)
#pragma unroll
                for (int j = 0; j < 4; j++)
                    st[(tn * 4 + j) * 17 + cw0 + p] = lo ? lw[p][j] : hw[p][j];
        }
        __syncthreads();
        unsigned* dst = (ph == 0 ? g_qh : ph == 1 ? g_ql : ph == 2 ? g_kh : g_kl)
                        + ((size_t)b * NN + n0) * 16;
        int row = tid >> 2, w0 = (tid & 3) * 4;
        unsigned t0 = st[row * 17 + w0 + 0], t1 = st[row * 17 + w0 + 1];
        unsigned t2 = st[row * 17 + w0 + 2], t3 = st[row * 17 + w0 + 3];
        *(uint4*)&dst[row * 16 + w0] = make_uint4(t0, t1, t2, t3);
    }
}

// ---------------- K_V2: tensor-core v projection (bf16 hi/lo 3-product) ----------------
// grid (64, BN), 256 thr, 8 warps = 8 c-blocks of 32; n-tile 64; k-chunks of 32.
struct Kv2Smem {
    unsigned Wh[256 * 20];  // Wv hi, [c-row][k-pair word], stride 20
    unsigned Wl[256 * 20];  // Wv lo residual
    unsigned Xh[64 * 20];   // x hi, [n-row][k-pair word]
    unsigned Xl[64 * 20];   // x lo residual
};

__global__ void __launch_bounds__(256) k_v2(const float* __restrict__ x,
                                            const float* __restrict__ Wv, const float* __restrict__ bv) {
    extern __shared__ Kv2Smem sv[];
    Kv2Smem& S = sv[0];
    int nb = blockIdx.x, b = blockIdx.y;
    int n0 = nb * 64;
    int tid = threadIdx.x;
    int warp = tid >> 5, lane = tid & 31, gid = lane >> 2, tg = lane & 3;
    int c0s = warp * 32;
    const float* xb = x + (size_t)b * CC * NN;
    // fragment lane bases (identical formulas to the validated S-stage)
    unsigned aoff = ((c0s + (lane & 15)) * 20 + ((lane >> 4) << 2)) * 4;
    unsigned WhA = sptr(S.Wh) + aoff, WlA = sptr(S.Wl) + aoff;
    unsigned boff = (((lane & 7) + ((lane & 16) >> 1)) * 20 + ((lane & 8) >> 1)) * 4;
    unsigned XhB = sptr(S.Xh) + boff, XlB = sptr(S.Xl) + boff;
    float acc[2][8][4];
#pragma unroll
    for (int m = 0; m < 2; m++)
#pragma unroll
        for (int n = 0; n < 8; n++)
#pragma unroll
            for (int e = 0; e < 4; e++) acc[m][n][e] = 0.f;

    for (int k0 = 0; k0 < CC; k0 += 32) {
        // ---- Wv chunk: thread = one c-row, 32 k values -> 16 hi words + 16 lo words ----
        {
            const float4* src = (const float4*)&Wv[(size_t)tid * CC + k0];
            float f[32];
#pragma unroll
            for (int q = 0; q < 8; q++) {
                float4 w4 = src[q];
                f[q * 4 + 0] = w4.x; f[q * 4 + 1] = w4.y;
                f[q * 4 + 2] = w4.z; f[q * 4 + 3] = w4.w;
            }
#pragma unroll
            for (int w = 0; w < 16; w++) {
                float a0 = f[2 * w], a1 = f[2 * w + 1];
                unsigned h0 = bf16bits(a0), h1 = bf16bits(a1);
                unsigned l0 = bf16bits(a0 - __uint_as_float(h0 << 16));
                unsigned l1 = bf16bits(a1 - __uint_as_float(h1 << 16));
                S.Wh[tid * 20 + w] = h0 | (h1 << 16);
                S.Wl[tid * 20 + w] = l0 | (l1 << 16);
            }
        }
        // ---- x chunk: thread = (k-pair kp, 4 n) -> Xh/Xl[n][kp] ----
        {
            int kp = tid >> 4, nn = (tid & 15) * 4;
            const float* s0 = xb + (size_t)(k0 + 2 * kp) * NN + n0 + nn;
            float4 xe = *(const float4*)s0;        // k = 2kp
            float4 xo = *(const float4*)(s0 + NN); // k = 2kp+1
            float ef[4] = {xe.x, xe.y, xe.z, xe.w};
            float of[4] = {xo.x, xo.y, xo.z, xo.w};
#pragma unroll
            for (int i = 0; i < 4; i++) {
                unsigned he = bf16bits(ef[i]), ho = bf16bits(of[i]);
                unsigned le = bf16bits(ef[i] - __uint_as_float(he << 16));
                unsigned lo = bf16bits(of[i] - __uint_as_float(ho << 16));
                S.Xh[(nn + i) * 20 + kp] = he | (ho << 16);
                S.Xl[(nn + i) * 20 + kp] = le | (lo << 16);
            }
        }
        __syncthreads();
        // ---- mma: 2 kk2 x (B frags hoisted) x 2 M-blocks x 8 N8 x 3 products ----
#pragma unroll
        for (int kk2 = 0; kk2 < 2; kk2++) {
            unsigned bh[4][4], bl[4][4];
#pragma unroll
            for (int np = 0; np < 4; np++) {
                unsigned ro = (unsigned)(np * 16 * 80) + kk2 * 32;
                ldsm4(XhB + ro, bh[np][0], bh[np][1], bh[np][2], bh[np][3]);
                ldsm4(XlB + ro, bl[np][0], bl[np][1], bl[np][2], bl[np][3]);
            }
#pragma unroll
            for (int mb = 0; mb < 2; mb++) {
                unsigned ah0, ah1, ah2, ah3, al0, al1, al2, al3;
                unsigned mo = (unsigned)(mb * 16 * 80) + kk2 * 32;
                ldsm4(WhA + mo, ah0, ah1, ah2, ah3);
                ldsm4(WlA + mo, al0, al1, al2, al3);
#pragma unroll
                for (int np = 0; np < 4; np++) {
                    mma16816(acc[mb][2 * np], ah0, ah1, ah2, ah3, bh[np][0], bh[np][1]);
                    mma16816(acc[mb][2 * np], ah0, ah1, ah2, ah3, bl[np][0], bl[np][1]);
                    mma16816(acc[mb][2 * np], al0, al1, al2, al3, bh[np][0], bh[np][1]);
                    mma16816(acc[mb][2 * np + 1], ah0, ah1, ah2, ah3, bh[np][2], bh[np][3]);
                    mma16816(acc[mb][2 * np + 1], ah0, ah1, ah2, ah3, bl[np][2], bl[np][3]);
                    mma16816(acc[mb][2 * np + 1], al0, al1, al2, al3, bh[np][2], bh[np][3]);
                }
            }
        }
        __syncthreads();
    }
    // ---- epilogue: bias + pack (even n, odd n) -> g_vtp[c][m2] ----
#pragma unroll
    for (int mb = 0; mb < 2; mb++) {
#pragma unroll
        for (int half = 0; half < 2; half++) {
            int c = c0s + mb * 16 + gid + half * 8;
            float bias = bv[c];
            unsigned* dst = g_vtp + ((size_t)b * CC + c) * (NN / 2) + (n0 >> 1);
#pragma unroll
            for (int nbk = 0; nbk < 8; nbk++) {
                float v0 = acc[mb][nbk][half * 2 + 0] + bias;   // n = nbk*8 + 2tg (even)
                float v1 = acc[mb][nbk][half * 2 + 1] + bias;   // n = nbk*8 + 2tg + 1 (odd)
                dst[nbk * 4 + tg] = bf16bits(v0) | (bf16bits(v1) << 16);
            }
        }
    }
}

// ---------------- KO8: j=128/512thr; single-barrier phase-B (R16-validated, unchanged) ----------------
struct Ko8Smem {
    unsigned ksh[128 * 20];
    unsigned ksl[128 * 20];
    unsigned qsh[3][64 * 20];
    unsigned qsl[3][64 * 20];
    unsigned As[2][128 * 36];  // bf16 P tile, double buffered
    unsigned Bs[3][256 * 36];  // v chunks triple buffered; phase-A q stream; epilogue fp32 staging
    float zsh[128];
};
#define QBUF_B (64 * 20 * 4)
#define VBUF_B (256 * 36 * 4)
#define ASBUF_B (128 * 36 * 4)
#define PA_HL  (256 * 20 * 4)
#define PA_BUF (2 * PA_HL)

__global__ void __launch_bounds__(512) k_o8(float* __restrict__ AM, const float* __restrict__ x,
                                            const float* __restrict__ gptr, float* __restrict__ outp) {
    extern __shared__ Ko8Smem s8[];
    Ko8Smem& S = s8[0];
    int jb = blockIdx.x, b = blockIdx.y;
    int j0 = jb * 128;
    int tid = threadIdx.x;
    if (tid < 128) S.zsh[tid] = 0.f;
    // K tiles once
    for (int u = tid; u < 1024; u += 512) {
        int bufl = u >> 9, r = (u >> 2) & 127, w = (u & 3) * 4;
        const unsigned* src = (bufl ? g_kl : g_kh) + ((size_t)b * NN + j0 + r) * 16 + w;
        unsigned* dst = (bufl ? S.ksl : S.ksh) + r * 20 + w;
        *(uint4*)dst = *(const uint4*)src;
    }
    __syncthreads();

    int warp = tid >> 5, lane = tid & 31, gid = lane >> 2, tg = lane & 3;
    int j0s = (warp & 7) * 16;
    int m0sB = (warp >> 3) * 32, m0sA = (warp >> 3) * 128;
    int wj = warp >> 2, wc = warp & 3;
    unsigned aoffS = ((j0s + (lane & 15)) * 20 + ((lane >> 4) << 2)) * 4;
    unsigned kshA = sptr(S.ksh) + aoffS, kslA = sptr(S.ksl) + aoffS;
    unsigned boffS = (((lane & 7) + ((lane & 16) >> 1)) * 20 + ((lane & 8) >> 1)) * 4;
    unsigned AsA = sptr(S.As[0]) + ((lane & 15) * 36 + ((lane >> 4) << 2)) * 4;
    unsigned boffO = ((((lane & 7) + ((lane & 16) >> 1)) + wc * 64) * 36 + ((lane & 8) >> 1)) * 4;
    unsigned qshS = sptr(S.qsh[0]), qslS = sptr(S.qsl[0]), BsS = sptr(S.Bs[0]);
    const unsigned* vbp = g_vtp + (size_t)b * CC * (NN / 2);

    // hoisted k A-fragments (loop-invariant across BOTH phases)
    unsigned ah2[2][4], al2[2][4];
    ldsm4(kshA + 0, ah2[0][0], ah2[0][1], ah2[0][2], ah2[0][3]);
    ldsm4(kshA + 32, ah2[1][0], ah2[1][1], ah2[1][2], ah2[1][3]);
    ldsm4(kslA + 0, al2[0][0], al2[0][1], al2[0][2], al2[0][3]);
    ldsm4(kslA + 32, al2[1][0], al2[1][1], al2[1][2], al2[1][3]);

    // ================= phase A: Z sweep, m-chunk 256, 16 iterations ================
    {
        for (int u = tid; u < 2048; u += 512) {
            int hl = u >> 10, r = (u >> 2) & 255, w4 = (u & 3) * 4;
            cpa16(BsS + hl * PA_HL + (r * 20 + w4) * 4,
                  (hl ? g_ql : g_qh) + ((size_t)b * NN + r) * 16 + w4);
        }
        asm volatile("cp.async.commit_group;");
    }
    float z0 = 0.f, z1 = 0.f;
    for (int it = 0; it < 16; it++) {
        if (it < 15) {
            int i0n = (it + 1) * 256;
            for (int u = tid; u < 2048; u += 512) {
                int hl = u >> 10, r = (u >> 2) & 255, w4 = (u & 3) * 4;
                cpa16(BsS + ((it + 1) & 1) * PA_BUF + hl * PA_HL + (r * 20 + w4) * 4,
                      (hl ? g_ql : g_qh) + ((size_t)b * NN + i0n + r) * 16 + w4);
            }
        }
        asm volatile("cp.async.commit_group;");
        asm volatile("cp.async.wait_group 1;");
        __syncthreads();
        unsigned qh_b = BsS + (it & 1) * PA_BUF + boffS;
        unsigned ql_b = qh_b + PA_HL;
#pragma unroll
        for (int tp = 0; tp < 16; tp += 2) {
            float d2[2][4];
#pragma unroll
            for (int a = 0; a < 2; a++)
#pragma unroll
                for (int e = 0; e < 4; e++) d2[a][e] = 0.f;
#pragma unroll
            for (int kk2 = 0; kk2 < 2; kk2++) {
                unsigned ro = (unsigned)((m0sA + tp * 8) * 80) + kk2 * 32;
                unsigned bh0, bh1, bh2, bh3, bl0, bl1, bl2, bl3;
                ldsm4(qh_b + ro, bh0, bh1, bh2, bh3);
                ldsm4(ql_b + ro, bl0, bl1, bl2, bl3);
                mma16816(d2[0], ah2[kk2][0], ah2[kk2][1], ah2[kk2][2], ah2[kk2][3], bh0, bh1);
                mma16816(d2[0], ah2[kk2][0], ah2[kk2][1], ah2[kk2][2], ah2[kk2][3], bl0, bl1);
                mma16816(d2[0], al2[kk2][0], al2[kk2][1], al2[kk2][2], al2[kk2][3], bh0, bh1);
                mma16816(d2[1], ah2[kk2][0], ah2[kk2][1], ah2[kk2][2], ah2[kk2][3], bh2, bh3);
                mma16816(d2[1], ah2[kk2][0], ah2[kk2][1], ah2[kk2][2], ah2[kk2][3], bl2, bl3);
                mma16816(d2[1], al2[kk2][0], al2[kk2][1], al2[kk2][2], al2[kk2][3], bh2, bh3);
            }
            z0 += ex2f(d2[0][0]) + ex2f(d2[0][1]) + ex2f(d2[1][0]) + ex2f(d2[1][1]);
            z1 += ex2f(d2[0][2]) + ex2f(d2[0][3]) + ex2f(d2[1][2]) + ex2f(d2[1][3]);
        }
    }
    z0 += __shfl_xor_sync(0xffffffffu, z0, 1);
    z0 += __shfl_xor_sync(0xffffffffu, z0, 2);
    z1 += __shfl_xor_sync(0xffffffffu, z1, 1);
    z1 += __shfl_xor_sync(0xffffffffu, z1, 2);
    if (tg == 0) {
        atomicAdd(&S.zsh[j0s + gid], z0);
        atomicAdd(&S.zsh[j0s + gid + 8], z1);
    }
    asm volatile("cp.async.wait_group 0;");
    __syncthreads();
    float rz0 = 1.f / S.zsh[j0s + gid], rz1 = 1.f / S.zsh[j0s + gid + 8];

    // ================= phase B: single barrier per tile; S(t) + O(t-1); direct AM store ================
    float acc[2][8][4];
#pragma unroll
    for (int a = 0; a < 2; a++)
#pragma unroll
        for (int n = 0; n < 8; n++)
#pragma unroll
            for (int c = 0; c < 4; c++) acc[a][n][c] = 0.f;
    float* AMrow = AM + ((size_t)b * NN + j0) * (size_t)NN;
    int qlf = tid >> 8, qlr = (tid >> 2) & 63, qlw = (tid & 3) * 4;
    {  // prologue: q(0) -> qbuf 0
        cpa16((qlf ? qslS : qshS) + (qlr * 20 + qlw) * 4,
              (qlf ? g_ql : g_qh) + ((size_t)b * NN + qlr) * 16 + qlw);
        asm volatile("cp.async.commit_group;");
    }
    for (int t = 0; t < 64; t++) {
        int m0 = t * 64;
        int qb = t - (t / 3) * 3;             // t % 3
        int qbn = (qb == 2) ? 0 : qb + 1;     // (t+1) % 3
        int vbp3 = (qb == 0) ? 2 : qb - 1;    // (t-1) % 3
        if (t < 63) {  // prefetch q(t+1) -> qbuf (t+1)%3
            const unsigned* qs = (qlf ? g_ql : g_qh) + ((size_t)b * NN + (m0 + 64) + qlr) * 16 + qlw;
            cpa16((qlf ? qslS : qshS) + qbn * QBUF_B + (qlr * 20 + qlw) * 4, qs);
        }
        // v(t) -> vbuf t%3
#pragma unroll
        for (int itv = 0; itv < 4; itv++) {
            int idx = itv * 512 + tid;
            int r = idx >> 3, ch = (idx & 7) * 4;
            cpa16(BsS + qb * VBUF_B + (r * 36 + ch) * 4,
                  vbp + (size_t)r * (NN / 2) + (m0 >> 1) + ch);
        }
        asm volatile("cp.async.commit_group;");
        asm volatile("cp.async.wait_group 1;");
        __syncthreads();  // the ONLY barrier this iteration
        // ---- S-mma(t): reads qbuf t%3 ----
        unsigned qshB = qshS + qb * QBUF_B + boffS;
        unsigned qslB = qslS + qb * QBUF_B + boffS;
        float d[4][4];
#pragma unroll
        for (int tt = 0; tt < 4; tt++)
#pragma unroll
            for (int e = 0; e < 4; e++) d[tt][e] = 0.f;
#pragma unroll
        for (int kk2 = 0; kk2 < 2; kk2++) {
#pragma unroll
            for (int tp = 0; tp < 4; tp += 2) {
                unsigned ro = (unsigned)((m0sB + tp * 8) * 80) + kk2 * 32;
                unsigned bh0, bh1, bh2, bh3, bl0, bl1, bl2, bl3;
                ldsm4(qshB + ro, bh0, bh1, bh2, bh3);
                ldsm4(qslB + ro, bl0, bl1, bl2, bl3);
                mma16816(d[tp], ah2[kk2][0], ah2[kk2][1], ah2[kk2][2], ah2[kk2][3], bh0, bh1);
                mma16816(d[tp], ah2[kk2][0], ah2[kk2][1], ah2[kk2][2], ah2[kk2][3], bl0, bl1);
                mma16816(d[tp], al2[kk2][0], al2[kk2][1], al2[kk2][2], al2[kk2][3], bh0, bh1);
                mma16816(d[tp + 1], ah2[kk2][0], ah2[kk2][1], ah2[kk2][2], ah2[kk2][3], bh2, bh3);
                mma16816(d[tp + 1], ah2[kk2][0], ah2[kk2][1], ah2[kk2][2], ah2[kk2][3], bl2, bl3);
                mma16816(d[tp + 1], al2[kk2][0], al2[kk2][1], al2[kk2][2], al2[kk2][3], bh2, bh3);
            }
        }
        // ---- O-mma(t-1): depth-1 B-fragment pipeline ----
        if (t > 0) {
            unsigned AsR = AsA + (unsigned)(((t - 1) & 1) * ASBUF_B);
            unsigned BsB = BsS + vbp3 * VBUF_B + boffO;
#pragma unroll
            for (int kk = 0; kk < 4; kk++) {
                unsigned a0[4], a1[4];
                ldsm4(AsR + (unsigned)((wj * 32) * 144 + kk * 32), a0[0], a0[1], a0[2], a0[3]);
                ldsm4(AsR + (unsigned)((wj * 32 + 16) * 144 + kk * 32), a1[0], a1[1], a1[2], a1[3]);
                unsigned bc0, bc1, bc2, bc3;
                ldsm4(BsB + (unsigned)(kk * 32), bc0, bc1, bc2, bc3);
#pragma unroll
                for (int ntp = 0; ntp < 4; ntp++) {
                    unsigned bn0 = 0, bn1 = 0, bn2 = 0, bn3 = 0;
                    if (ntp < 3)
                        ldsm4(BsB + (unsigned)(((ntp + 1) * 16) * 144 + kk * 32), bn0, bn1, bn2, bn3);
                    mma16816(acc[0][2 * ntp], a0[0], a0[1], a0[2], a0[3], bc0, bc1);
                    mma16816(acc[1][2 * ntp], a1[0], a1[1], a1[2], a1[3], bc0, bc1);
                    mma16816(acc[0][2 * ntp + 1], a0[0], a0[1], a0[2], a0[3], bc2, bc3);
                    mma16816(acc[1][2 * ntp + 1], a1[0], a1[1], a1[2], a1[3], bc2, bc3);
                    bc0 = bn0; bc1 = bn1; bc2 = bn2; bc3 = bn3;
                }
            }
        }
        // ---- exp(t): normalize, direct AM store, stage bf16 P into As[t&1] ----
        unsigned* AsW = S.As[t & 1];
#pragma unroll
        for (int tt = 0; tt < 4; tt++) {
            float e0 = ex2f(d[tt][0]) * rz0;
            float e1 = ex2f(d[tt][1]) * rz0;
            float e2 = ex2f(d[tt][2]) * rz1;
            float e3 = ex2f(d[tt][3]) * rz1;
            int col = m0 + m0sB + tt * 8 + 2 * tg;
            *(float2*)&AMrow[(size_t)(j0s + gid) * NN + col] = make_float2(e0, e1);
            *(float2*)&AMrow[(size_t)(j0s + gid + 8) * NN + col] = make_float2(e2, e3);
            AsW[(j0s + gid) * 36 + (m0sB >> 1) + tt * 4 + tg] = bf16bits(e0) | (bf16bits(e1) << 16);
            AsW[(j0s + gid + 8) * 36 + (m0sB >> 1) + tt * 4 + tg] = bf16bits(e2) | (bf16bits(e3) << 16);
        }
    }
    // ---- drain: O(63) reads As[1], vbuf 63%3=0 ----
    asm volatile("cp.async.wait_group 0;");
    __syncthreads();
    {
        unsigned AsR = AsA + (unsigned)ASBUF_B;
        unsigned BsB = BsS + 0 * VBUF_B + boffO;
#pragma unroll
        for (int kk = 0; kk < 4; kk++) {
            unsigned a0[4], a1[4];
            ldsm4(AsR + (unsigned)((wj * 32) * 144 + kk * 32), a0[0], a0[1], a0[2], a0[3]);
            ldsm4(AsR + (unsigned)((wj * 32 + 16) * 144 + kk * 32), a1[0], a1[1], a1[2], a1[3]);
#pragma unroll
            for (int ntp = 0; ntp < 4; ntp++) {
                unsigned b0a, b1a, b0b, b1b;
                ldsm4(BsB + (unsigned)((ntp * 16) * 144 + kk * 32), b0a, b1a, b0b, b1b);
                mma16816(acc[0][2 * ntp], a0[0], a0[1], a0[2], a0[3], b0a, b1a);
                mma16816(acc[1][2 * ntp], a1[0], a1[1], a1[2], a1[3], b0a, b1a);
                mma16816(acc[0][2 * ntp + 1], a0[0], a0[1], a0[2], a0[3], b0b, b1b);
                mma16816(acc[1][2 * ntp + 1], a1[0], a1[1], a1[2], a1[3], b0b, b1b);
            }
        }
    }
    __syncthreads();
    // ---- epilogue: out = x + gamma*o; 4 phases of 32 j rows ----
    float gma = __ldg(gptr);
    float* fBs = (float*)S.Bs[0];  // 32 x 256 fp32
    int ec = tid & 255, ejh = tid >> 8;
    for (int h = 0; h < 4; h++) {
        if (wj == h) {
#pragma unroll
            for (int jt = 0; jt < 2; jt++)
#pragma unroll
                for (int nt = 0; nt < 8; nt++) {
                    int rr = jt * 16 + gid;
                    int cc2 = wc * 64 + nt * 8 + tg * 2;
                    fBs[rr * 256 + cc2]           = acc[jt][nt][0];
                    fBs[rr * 256 + cc2 + 1]       = acc[jt][nt][1];
                    fBs[(rr + 8) * 256 + cc2]     = acc[jt][nt][2];
                    fBs[(rr + 8) * 256 + cc2 + 1] = acc[jt][nt][3];
                }
        }
        __syncthreads();
        const float* xrow = x + ((size_t)b * CC + ec) * NN + j0 + h * 32 + ejh * 16;
        float* orow = outp + ((size_t)b * CC + ec) * NN + j0 + h * 32 + ejh * 16;
#pragma unroll
        for (int jq = 0; jq < 4; jq++) {
            float4 o;
            o.x = fBs[(ejh * 16 + jq * 4 + 0) * 256 + ec];
            o.y = fBs[(ejh * 16 + jq * 4 + 1) * 256 + ec];
            o.z = fBs[(ejh * 16 + jq * 4 + 2) * 256 + ec];
            o.w = fBs[(ejh * 16 + jq * 4 + 3) * 256 + ec];
            float4 xr = *(const float4*)(xrow + jq * 4);
            float4 res = {xr.x + gma * o.x, xr.y + gma * o.y, xr.z + gma * o.z, xr.w + gma * o.w};
            *(float4*)(orow + jq * 4) = res;
        }
        __syncthreads();
    }
}

// ---------------- launch ----------------
extern "C" void kernel_launch(void* const* d_in, const int* in_sizes, int n_in,
                              void* d_out, int out_size) {
    const float* x  = (const float*)d_in[0];
    const float* Wq = (const float*)d_in[1];
    const float* bq = (const float*)d_in[2];
    const float* Wk = (const float*)d_in[3];
    const float* bk = (const float*)d_in[4];
    const float* Wv = (const float*)d_in[5];
    const float* bv = (const float*)d_in[6];
    const float* gm = (const float*)d_in[7];
    float* outp = (float*)d_out;
    float* AM = outp + (size_t)BN * CC * 64 * 64;

    cudaFuncSetAttribute(k_o8, cudaFuncAttributeMaxDynamicSharedMemorySize,
                         (int)sizeof(Ko8Smem));
    cudaFuncSetAttribute(k_v2, cudaFuncAttributeMaxDynamicSharedMemorySize,
                         (int)sizeof(Kv2Smem));

    k_qk<<<dim3(64, BN), 256>>>(x, Wq, bq, Wk, bk);
    k_v2<<<dim3(64, BN), 256, sizeof(Kv2Smem)>>>(x, Wv, bv);
    k_o8<<<dim3(32, BN), 512, sizeof(Ko8Smem)>>>(AM, x, gm, outp);
}